// round 17
// baseline (speedup 1.0000x reference)
#include <cuda_runtime.h>
#include <cuda_fp16.h>
#include <cstdint>

#define KC   512
#define DD   64
#define TPB  128
#define BN   64
#define LDA  72      // fp16 elems per row (144B)
#define ROWB 144

#define OFF_AH   0                     // 64 x 144B (h of x)
#define OFF_AM   9216                  // 64 x 144B (m of x)
#define OFF_BH   18432                 // 128 x 144B (H of codes quarter)
#define OFF_BM   36864                 // 128 x 144B (M of codes quarter)
#define OFF_HWW  55296                 // 128 f32
#define OFF_SBV  55808                 // 64x2 f32
#define OFF_SBI  56320                 // 64x2 i32
#define OFF_KIDX 56832                 // 64 i32
#define OFF_SRED 57088                 // 4 dbl
#define SMEM_TOTAL 57152               // x4 CTAs/SM fits 228KB + 64K regs exactly

#define NPRE 16                        // producer blocks for codebook pre-split
#define NBUCKET 64                     // loss atomic buckets

__device__ __align__(16) __half g_bh[KC * LDA];   // pre-split codebook, h-term [k][d]
__device__ __align__(16) __half g_bm[KC * LDA];   // m-term
__device__ __align__(16) float  g_hww[KC];        // 0.5*||w||^2
__device__ double   g_loss_arr[NBUCKET];
__device__ unsigned g_ctr;
__device__ unsigned g_pre_ctr;

#define LDSM4(r0, r1, r2, r3, addr) \
    asm volatile("ldmatrix.sync.aligned.m8n8.x4.shared.b16 {%0,%1,%2,%3}, [%4];" \
                 : "=r"(r0), "=r"(r1), "=r"(r2), "=r"(r3) : "r"(addr))

#define MMA(d, a, b) \
    asm volatile("mma.sync.aligned.m16n8k16.row.col.f32.f16.f16.f32 " \
                 "{%0,%1,%2,%3}, {%4,%5,%6,%7}, {%8,%9}, {%0,%1,%2,%3};" \
                 : "+f"((d)[0]), "+f"((d)[1]), "+f"((d)[2]), "+f"((d)[3]) \
                 : "r"((a)[0]), "r"((a)[1]), "r"((a)[2]), "r"((a)[3]), \
                   "r"((b)[0]), "r"((b)[1]))

#define CPA16(dst, src) \
    asm volatile("cp.async.cg.shared.global [%0], [%1], 16;" :: "r"(dst), "l"(src))

// issue B quarter qtr copy (H + M + hww) as one commit group
__device__ __forceinline__ void issue_quarter(uint32_t sb, int qtr, int t)
{
    const char* srcH = (const char*)g_bh + (size_t)qtr * 128 * ROWB;
    const char* srcM = (const char*)g_bm + (size_t)qtr * 128 * ROWB;
    #pragma unroll
    for (int i = t; i < 1152; i += TPB) {     // 128*144B / 16B
        CPA16(sb + OFF_BH + i * 16, srcH + i * 16);
        CPA16(sb + OFF_BM + i * 16, srcM + i * 16);
    }
    if (t < 32) CPA16(sb + OFF_HWW + t * 16, (const char*)g_hww + qtr * 512 + t * 16);
    asm volatile("cp.async.commit_group;");
}

__global__ void __launch_bounds__(TPB, 4)
vq_main_kernel(const float* __restrict__ x, const float* __restrict__ emb,
               float* __restrict__ out_q, float* __restrict__ out_idx,
               float* __restrict__ out_loss, int n_rows, double inv_count)
{
    extern __shared__ char smem[];
    const uint32_t sb = (uint32_t)__cvta_generic_to_shared(smem);
    const int t = threadIdx.x, lane = t & 31, w = t >> 5;
    const int wm = w >> 1, wn = w & 1;       // 2 m-warps x 2 n-warps
    const int rowbase = blockIdx.x * BN;

    // ---- producer blocks: pre-split one 32-code slice of the codebook ----
    if (blockIdx.x < NPRE) {
        const int c  = blockIdx.x * 32 + (t & 31);   // code
        const int d0 = (t >> 5) * 16;                // 16-d segment base
        float s = 0.f;
        uint32_t hw[8], mw[8];
        #pragma unroll
        for (int j = 0; j < 8; j++) {
            float e0 = __ldg(emb + (size_t)(d0 + 2 * j) * KC + c);
            float e1 = __ldg(emb + (size_t)(d0 + 2 * j + 1) * KC + c);
            s = fmaf(e1, e1, fmaf(e0, e0, s));
            __half h0 = __float2half_rn(e0), h1 = __float2half_rn(e1);
            __half m0 = __float2half_rn(e0 - __half2float(h0));
            __half m1 = __float2half_rn(e1 - __half2float(h1));
            hw[j] = (uint32_t)__half_as_ushort(h0) | ((uint32_t)__half_as_ushort(h1) << 16);
            mw[j] = (uint32_t)__half_as_ushort(m0) | ((uint32_t)__half_as_ushort(m1) << 16);
        }
        *(uint4*)(g_bh + (size_t)c * LDA + d0)     = make_uint4(hw[0], hw[1], hw[2], hw[3]);
        *(uint4*)(g_bh + (size_t)c * LDA + d0 + 8) = make_uint4(hw[4], hw[5], hw[6], hw[7]);
        *(uint4*)(g_bm + (size_t)c * LDA + d0)     = make_uint4(mw[0], mw[1], mw[2], mw[3]);
        *(uint4*)(g_bm + (size_t)c * LDA + d0 + 8) = make_uint4(mw[4], mw[5], mw[6], mw[7]);
        float* sp = (float*)(smem + OFF_BH);    // scratch before quarter loop
        sp[(t >> 5) * 32 + (t & 31)] = s;
        __syncthreads();
        if (t < 32)
            g_hww[blockIdx.x * 32 + t] = 0.5f * (sp[t] + sp[32 + t] + sp[64 + t] + sp[96 + t]);
        __threadfence();
        __syncthreads();
        if (t == 0) atomicAdd(&g_pre_ctr, 1u);
    }

    // ---- load this block's x rows into registers (independent of producers) ----
    float4 xf[8];
    {
        const int row = t >> 1, hseg = (t & 1) * 32;
        const bool valid = (rowbase + row) < n_rows;
        const float4* xr = (const float4*)(x + (size_t)(rowbase + row) * DD + hseg);
        #pragma unroll
        for (int j = 0; j < 8; j++)
            xf[j] = valid ? xr[j] : make_float4(0.f, 0.f, 0.f, 0.f);
    }

    // ---- wait for all producers (wave-1 residency guarantees progress) ----
    if (t == 0) {
        while (atomicAdd(&g_pre_ctr, 0u) < NPRE) __nanosleep(64);
        __threadfence();
    }
    __syncthreads();

    // ---- issue quarter 0's B copy NOW; A convert/store runs under it ----
    issue_quarter(sb, 0, t);

    // ---- A split: registers -> h (AH) + m (AM) fp16 smem tiles ----
    {
        const int row = t >> 1, hseg = (t & 1) * 32;
        __half* ah = (__half*)(smem + OFF_AH) + row * LDA + hseg;
        __half* am = (__half*)(smem + OFF_AM) + row * LDA + hseg;
        #pragma unroll
        for (int j = 0; j < 8; j++) {
            float e[4] = {xf[j].x, xf[j].y, xf[j].z, xf[j].w};
            __half h[4], m[4];
            #pragma unroll
            for (int p = 0; p < 4; p++) {
                h[p] = __float2half_rn(e[p]);
                m[p] = __float2half_rn(e[p] - __half2float(h[p]));
            }
            *(__half2*)(ah + 4 * j)     = __halves2half2(h[0], h[1]);
            *(__half2*)(ah + 4 * j + 2) = __halves2half2(h[2], h[3]);
            *(__half2*)(am + 4 * j)     = __halves2half2(m[0], m[1]);
            *(__half2*)(am + 4 * j + 2) = __halves2half2(m[2], m[3]);
        }
    }

    float best[4];
    int   bk[4];
    #pragma unroll
    for (int s = 0; s < 4; s++) { best[s] = -3.402823466e38f; bk[s] = 0; }

    const uint32_t a_off = (uint32_t)((wm * 32 + (lane & 15)) * ROWB + (((lane >> 4) << 3) << 1));
    const uint32_t b_off = (uint32_t)(((lane & 7) + ((lane >> 4) << 3) + wn * 64) * ROWB
                                      + ((((lane >> 3) & 1) << 3) << 1));

    #pragma unroll 1
    for (int q = 0; q < 4; q++) {
        const int qbase = q * 128;
        asm volatile("cp.async.wait_group 0;" ::: "memory");
        __syncthreads();   // B quarter + (q==0: A tiles) visible to all warps

        // ---- MMA: acc = x.w - 0.5||w||^2 via hH + mH + hM, fp32 accum ----
        float acc[2][8][4];
        {
            const float* hww = (const float*)(smem + OFF_HWW);
            #pragma unroll
            for (int nt = 0; nt < 8; nt++) {
                float2 hv = *(const float2*)(hww + wn * 64 + nt * 8 + 2 * (lane & 3));
                #pragma unroll
                for (int mt = 0; mt < 2; mt++) {
                    acc[mt][nt][0] = -hv.x; acc[mt][nt][1] = -hv.y;
                    acc[mt][nt][2] = -hv.x; acc[mt][nt][3] = -hv.y;
                }
            }
        }
        #pragma unroll
        for (int kc = 0; kc < 4; kc++) {
            const uint32_t ka = (uint32_t)(kc * 32);
            uint32_t ah[2][4], am[2][4], bb[8][2];
            LDSM4(ah[0][0], ah[0][1], ah[0][2], ah[0][3], sb + OFF_AH + a_off + ka);
            LDSM4(ah[1][0], ah[1][1], ah[1][2], ah[1][3], sb + OFF_AH + a_off + ka + 16 * ROWB);
            LDSM4(am[0][0], am[0][1], am[0][2], am[0][3], sb + OFF_AM + a_off + ka);
            LDSM4(am[1][0], am[1][1], am[1][2], am[1][3], sb + OFF_AM + a_off + ka + 16 * ROWB);
            #pragma unroll
            for (int ng = 0; ng < 4; ng++)
                LDSM4(bb[2 * ng][0], bb[2 * ng][1], bb[2 * ng + 1][0], bb[2 * ng + 1][1],
                      sb + OFF_BH + b_off + ka + ng * 16 * ROWB);
            #pragma unroll
            for (int mt = 0; mt < 2; mt++)
                #pragma unroll
                for (int nt = 0; nt < 8; nt++) {
                    MMA(acc[mt][nt], ah[mt], bb[nt]);   // h.H
                    MMA(acc[mt][nt], am[mt], bb[nt]);   // m.H
                }
            #pragma unroll
            for (int ng = 0; ng < 4; ng++)
                LDSM4(bb[2 * ng][0], bb[2 * ng][1], bb[2 * ng + 1][0], bb[2 * ng + 1][1],
                      sb + OFF_BM + b_off + ka + ng * 16 * ROWB);
            #pragma unroll
            for (int mt = 0; mt < 2; mt++)
                #pragma unroll
                for (int nt = 0; nt < 8; nt++)
                    MMA(acc[mt][nt], ah[mt], bb[nt]);   // h.M
        }

        // ---- refill: all warps done reading -> next quarter's copy under the scan ----
        if (q < 3) {
            __syncthreads();
            issue_quarter(sb, q + 1, t);
        }

        // ---- scan: strict >, ascending cols -> first-index argmin semantics ----
        #pragma unroll
        for (int mt = 0; mt < 2; mt++)
            #pragma unroll
            for (int nt = 0; nt < 8; nt++) {
                const int c0 = qbase + wn * 64 + nt * 8 + 2 * (lane & 3);
                #pragma unroll
                for (int rh = 0; rh < 2; rh++) {
                    const int s = mt * 2 + rh;
                    float v0 = acc[mt][nt][rh * 2 + 0];
                    float v1 = acc[mt][nt][rh * 2 + 1];
                    if (v0 > best[s]) { best[s] = v0; bk[s] = c0; }
                    if (v1 > best[s]) { best[s] = v1; bk[s] = c0 + 1; }
                }
            }
    }
    __syncthreads();

    // ---- per-row reduce: width-4 shfl, then combine the 2 n-warps ----
    #pragma unroll
    for (int s = 0; s < 4; s++) {
        float v = best[s]; int bi = bk[s];
        #pragma unroll
        for (int off = 1; off <= 2; off <<= 1) {
            float ov = __shfl_xor_sync(0xffffffffu, v, off);
            int   oi = __shfl_xor_sync(0xffffffffu, bi, off);
            if (ov > v || (ov == v && oi < bi)) { v = ov; bi = oi; }
        }
        if ((lane & 3) == 0) {
            int row = wm * 32 + (s >> 1) * 16 + (s & 1) * 8 + (lane >> 2);
            ((float*)(smem + OFF_SBV))[row * 2 + wn] = v;
            ((int*)(smem + OFF_SBI))[row * 2 + wn] = bi;
        }
    }
    __syncthreads();
    if (t < BN) {
        float v0 = ((float*)(smem + OFF_SBV))[t * 2 + 0];
        float v1 = ((float*)(smem + OFF_SBV))[t * 2 + 1];
        int   i0 = ((int*)(smem + OFF_SBI))[t * 2 + 0];
        int   i1 = ((int*)(smem + OFF_SBI))[t * 2 + 1];
        int k = (v1 > v0 || (v1 == v0 && i1 < i0)) ? i1 : i0;
        ((int*)(smem + OFF_KIDX))[t] = k;
        if (rowbase + t < n_rows) out_idx[rowbase + t] = (float)k;
    }
    __syncthreads();

    // ---- epilogue: q = h+m from pre-split (contiguous 144B gather), loss ----
    double lsum = 0.0;
    {
        const int row = t >> 1, hseg = (t & 1) * 32;
        const int grow = rowbase + row;
        if (grow < n_rows) {
            const int k = ((int*)(smem + OFF_KIDX))[row];
            const __half* gh = g_bh + (size_t)k * LDA + hseg;
            const __half* gm = g_bm + (size_t)k * LDA + hseg;
            const __half* ahp = (const __half*)(smem + OFF_AH) + row * LDA + hseg;
            const __half* amp = (const __half*)(smem + OFF_AM) + row * LDA + hseg;
            float4* qo = (float4*)(out_q + (size_t)grow * DD + hseg);
            #pragma unroll
            for (int j = 0; j < 8; j++) {
                float2 wh0 = __half22float2(*(const __half2*)(gh + 4 * j));
                float2 wh1 = __half22float2(*(const __half2*)(gh + 4 * j + 2));
                float2 wm0 = __half22float2(*(const __half2*)(gm + 4 * j));
                float2 wm1 = __half22float2(*(const __half2*)(gm + 4 * j + 2));
                float q0 = wh0.x + wm0.x, q1 = wh0.y + wm0.y;
                float q2 = wh1.x + wm1.x, q3 = wh1.y + wm1.y;
                qo[j] = make_float4(q0, q1, q2, q3);
                float2 a0 = __half22float2(*(const __half2*)(ahp + 4 * j));
                float2 a1 = __half22float2(*(const __half2*)(ahp + 4 * j + 2));
                float2 b0 = __half22float2(*(const __half2*)(amp + 4 * j));
                float2 b1 = __half22float2(*(const __half2*)(amp + 4 * j + 2));
                float e0 = q0 - (a0.x + b0.x);
                float e1 = q1 - (a0.y + b0.y);
                float e2 = q2 - (a1.x + b1.x);
                float e3 = q3 - (a1.y + b1.y);
                lsum += (double)(e0 * e0 + e1 * e1 + e2 * e2 + e3 * e3);
            }
        }
    }

    // ---- loss reduction -> bucketed atomic; last block finalizes + resets ----
    #pragma unroll
    for (int off = 16; off; off >>= 1) lsum += __shfl_down_sync(0xffffffffu, lsum, off);
    double* sred = (double*)(smem + OFF_SRED);
    if (lane == 0) sred[w] = lsum;
    __syncthreads();
    if (t == 0) {
        double v = sred[0] + sred[1] + sred[2] + sred[3];
        atomicAdd(&g_loss_arr[blockIdx.x & (NBUCKET - 1)], v);
        __threadfence();
        unsigned prev = atomicAdd(&g_ctr, 1u);
        if (prev == gridDim.x - 1) {
            __threadfence();
            double total = 0.0;
            #pragma unroll
            for (int i = 0; i < NBUCKET; i++) {
                total += g_loss_arr[i];
                g_loss_arr[i] = 0.0;   // reset for next graph replay
            }
            *out_loss = (float)(1.25 * total * inv_count);
            g_ctr = 0u;
            g_pre_ctr = 0u;
        }
    }
}

extern "C" void kernel_launch(void* const* d_in, const int* in_sizes, int n_in,
                              void* d_out, int out_size)
{
    const float* x   = (const float*)d_in[0];   // [N, 64]
    const float* emb = (const float*)d_in[1];   // [64, 512]

    const int n_rows = in_sizes[0] / DD;
    float* out      = (float*)d_out;
    float* out_q    = out;
    float* out_idx  = out + (size_t)n_rows * DD;
    float* out_loss = out_idx + n_rows;

    cudaFuncSetAttribute(vq_main_kernel,
                         cudaFuncAttributeMaxDynamicSharedMemorySize, SMEM_TOTAL);

    int grid = (n_rows + BN - 1) / BN;   // 1024

    vq_main_kernel<<<grid, TPB, SMEM_TOTAL>>>(x, emb, out_q, out_idx, out_loss,
                                              n_rows, 1.0 / ((double)n_rows * (double)DD));
}